// round 1
// baseline (speedup 1.0000x reference)
#include <cuda_runtime.h>

#define N_NODES 50000
#define N_EDGES 800000
#define D_FEAT  64
#define ROWS_PER_BLOCK 8   // 8 warps/block, one row per warp

// out[r][:] = sum_{e: row_idx[e]==r} vals[e] * embeds[col_idx[e]][:]
// row_idx is sorted ascending. Warp-per-row: 32 lanes x float2 = 64 dims.
__global__ __launch_bounds__(ROWS_PER_BLOCK * 32)
void gcn_spmm_kernel(const int* __restrict__ row_idx,
                     const int* __restrict__ col_idx,
                     const float* __restrict__ vals,
                     const float* __restrict__ embeds,
                     float* __restrict__ out) {
    __shared__ int s_ptr[ROWS_PER_BLOCK + 1];

    const int tid  = threadIdx.x;
    const int base = blockIdx.x * ROWS_PER_BLOCK;

    // Threads 0..8 each find lower_bound(row_idx, base + t): first edge with
    // row_idx[e] >= target. Independent per-lane binary searches (same warp,
    // no divergence problem — one LDG per step with 9 active lanes).
    if (tid <= ROWS_PER_BLOCK) {
        const int target = base + tid;
        int lo = 0, hi = N_EDGES;
        while (lo < hi) {
            const int mid = (lo + hi) >> 1;
            const int v = __ldg(row_idx + mid);
            if (v < target) lo = mid + 1; else hi = mid;
        }
        s_ptr[tid] = lo;
    }
    __syncthreads();

    const int wid  = tid >> 5;
    const int lane = tid & 31;
    const int row  = base + wid;           // grid sized so row < N_NODES always

    const int start = s_ptr[wid];
    const int end   = s_ptr[wid + 1];

    const float2* __restrict__ emb2 = reinterpret_cast<const float2*>(embeds);

    float2 acc = make_float2(0.0f, 0.0f);

    int e = start;
    // Unroll by 2 for memory-level parallelism (independent gathers).
    for (; e + 1 < end; e += 2) {
        const int   c0 = __ldg(col_idx + e);
        const int   c1 = __ldg(col_idx + e + 1);
        const float v0 = __ldg(vals + e);
        const float v1 = __ldg(vals + e + 1);
        const float2 x0 = __ldg(emb2 + (size_t)c0 * 32 + lane);
        const float2 x1 = __ldg(emb2 + (size_t)c1 * 32 + lane);
        acc.x = fmaf(v0, x0.x, acc.x);
        acc.y = fmaf(v0, x0.y, acc.y);
        acc.x = fmaf(v1, x1.x, acc.x);
        acc.y = fmaf(v1, x1.y, acc.y);
    }
    if (e < end) {
        const int   c0 = __ldg(col_idx + e);
        const float v0 = __ldg(vals + e);
        const float2 x0 = __ldg(emb2 + (size_t)c0 * 32 + lane);
        acc.x = fmaf(v0, x0.x, acc.x);
        acc.y = fmaf(v0, x0.y, acc.y);
    }

    // Coalesced 256B row store. Rows with no edges write zeros (required:
    // d_out is poisoned before timing).
    reinterpret_cast<float2*>(out)[(size_t)row * 32 + lane] = acc;
}

extern "C" void kernel_launch(void* const* d_in, const int* in_sizes, int n_in,
                              void* d_out, int out_size) {
    const int*   row_idx = (const int*)  d_in[0];
    const int*   col_idx = (const int*)  d_in[1];
    const float* vals    = (const float*)d_in[2];
    const float* embeds  = (const float*)d_in[3];
    float*       out     = (float*)d_out;

    const int blocks = N_NODES / ROWS_PER_BLOCK;   // 50000 / 8 = 6250 exactly
    gcn_spmm_kernel<<<blocks, ROWS_PER_BLOCK * 32>>>(row_idx, col_idx, vals,
                                                     embeds, out);
}